// round 2
// baseline (speedup 1.0000x reference)
#include <cuda_runtime.h>
#include <math.h>

#define BB 32
#define CC 64
#define TT_ 128
#define VV 25
#define RR 8
#define TS 9
#define OUTC 64

// scratch (allocation-free rule: device globals)
__device__ float g_dbuf[BB * RR * VV * VV];          // d[b,r,j,i]  32*8*625 = 160000
__device__ float g_zbuf[(size_t)BB * CC * TT_ * VV]; // z[b,c,t,i]  6,553,600

// ---------------- kernel A: mean over T, x1/x2, d=tanh(x1-x2) ----------------
__global__ void __launch_bounds__(256) kA(const float* __restrict__ x,
                                          const float* __restrict__ w1, const float* __restrict__ b1,
                                          const float* __restrict__ w2, const float* __restrict__ b2) {
    int b = blockIdx.x;
    int tid = threadIdx.x;
    __shared__ float xm[CC * VV];          // mean_t x[b,c,:,v]
    __shared__ float x1s[RR * VV];
    __shared__ float x2s[RR * VV];

    for (int idx = tid; idx < CC * VV; idx += 256) {
        int c = idx / VV, v = idx % VV;
        const float* p = x + ((size_t)(b * CC + c) * TT_) * VV + v;
        float s = 0.f;
#pragma unroll 8
        for (int t = 0; t < TT_; t++) s += p[t * VV];
        xm[idx] = s * (1.0f / (float)TT_);
    }
    __syncthreads();

    // FIX (R1): 2*RR*VV = 400 > blockDim; must grid-stride, not mask.
    for (int q = tid; q < 2 * RR * VV; q += 256) {
        int which = q / (RR * VV);
        int idx = q % (RR * VV);
        int r = idx / VV, v = idx % VV;
        const float* w = which ? w2 : w1;
        float s = 0.f;
#pragma unroll 8
        for (int c = 0; c < CC; c++) s = fmaf(w[r * CC + c], xm[c * VV + v], s);
        s += (which ? b2 : b1)[r];
        (which ? x2s : x1s)[idx] = s;
    }
    __syncthreads();

    float* db = g_dbuf + b * (RR * VV * VV);
    for (int idx = tid; idx < RR * VV * VV; idx += 256) {
        int r = idx / (VV * VV);
        int rem = idx % (VV * VV);
        int j = rem / VV, i = rem % VV;
        db[idx] = tanhf(x1s[r * VV + j] - x2s[r * VV + i]);
    }
}

// ---------------- kernel B: build W[j,k,i] + dynamic conv -> z ----------------
// One block per (c, b). z[t,i] = sum_{j,k} xpad[t+k][j] * W[j,i,k]
__global__ void __launch_bounds__(256) kB(const float* __restrict__ x,
                                          const float* __restrict__ A,
                                          const float* __restrict__ w4, const float* __restrict__ b4) {
    int c = blockIdx.x;
    int b = blockIdx.y;
    int tid = threadIdx.x;

    __shared__ __align__(16) float W3s[VV * TS * VV];   // [j][k][i]  5625 floats
    __shared__ __align__(16) float xsT[VV * 140];       // [j][s], s in [0,136), pad stride 140

    const float* db = g_dbuf + b * (RR * VV * VV);

    // Build W: W[j,i,k] = A[j,i] + b4[c*9+k] + sum_r w4[c*9+k, r] * d[r,j,i]
    for (int p = tid; p < VV * VV; p += 256) {
        int j = p / VV, i = p % VV;
        float dr[RR];
#pragma unroll
        for (int r = 0; r < RR; r++) dr[r] = __ldg(db + r * (VV * VV) + p);
        float a = __ldg(A + p);
#pragma unroll
        for (int k = 0; k < TS; k++) {
            int o = c * TS + k;
            float s = a + __ldg(b4 + o);
#pragma unroll
            for (int r = 0; r < RR; r++) s = fmaf(__ldg(w4 + o * RR + r), dr[r], s);
            W3s[(j * TS + k) * VV + i] = s;
        }
    }

    // Stage x transposed + causal left pad of 8 zeros: xsT[j][8+t] = x[b,c,t,j]
    for (int idx = tid; idx < VV * 8; idx += 256) {
        int j = idx / 8, s0 = idx % 8;
        xsT[j * 140 + s0] = 0.f;
    }
    const float* xp = x + (size_t)(b * CC + c) * (TT_ * VV);
    for (int idx = tid; idx < TT_ * VV; idx += 256) {
        int t = idx / VV, j = idx % VV;
        xsT[j * 140 + t + 8] = xp[idx];
    }
    __syncthreads();

    int warp = tid >> 5, lane = tid & 31;
    int t0 = warp * 16;  // 8 warps * 16 t = 128

    if (lane < VV) {
        float acc[16];
#pragma unroll
        for (int q = 0; q < 16; q++) acc[q] = 0.f;

        for (int j = 0; j < VV; j++) {
            // 24 consecutive padded-time samples, 16B-aligned (t0 % 16 == 0, stride 140 % 4 == 0)
            float xr[24];
            const float4* xv = reinterpret_cast<const float4*>(&xsT[j * 140 + t0]);
#pragma unroll
            for (int q = 0; q < 6; q++) {
                float4 v = xv[q];
                xr[4 * q + 0] = v.x; xr[4 * q + 1] = v.y;
                xr[4 * q + 2] = v.z; xr[4 * q + 3] = v.w;
            }
#pragma unroll
            for (int k = 0; k < TS; k++) {
                float w = W3s[(j * TS + k) * VV + lane];
#pragma unroll
                for (int q = 0; q < 16; q++) acc[q] = fmaf(xr[q + k], w, acc[q]);
            }
        }
        float* zp = g_zbuf + (size_t)(b * CC + c) * (TT_ * VV) + lane;
#pragma unroll
        for (int q = 0; q < 16; q++) zp[(t0 + q) * VV] = acc[q];
    }
}

// ---------------- kernel C: out[b,o,t,v] = sum_c w3[o,c] z[b,c,t,v] + b3 ----------------
// block = (b, 64-wide tv tile); 256 threads: tv = tid%64, o-group = tid/64 (16 o each)
__global__ void __launch_bounds__(256) kC(const float* __restrict__ w3, const float* __restrict__ b3,
                                          float* __restrict__ out) {
    int b = blockIdx.y;
    int tv0 = blockIdx.x * 64;
    int tid = threadIdx.x;

    __shared__ __align__(16) float zs[CC * 64];
    __shared__ __align__(16) float w3s[OUTC * CC];

    const float* zb = g_zbuf + (size_t)b * CC * (TT_ * VV);
    for (int idx = tid; idx < CC * 64; idx += 256) {
        int cc = idx >> 6, u = idx & 63;
        zs[idx] = zb[cc * (TT_ * VV) + tv0 + u];
        w3s[idx] = w3[idx];
    }
    __syncthreads();

    int tv = tid & 63, og = tid >> 6;  // og in [0,4), each owns 16 output channels
    float acc[16];
#pragma unroll
    for (int oo = 0; oo < 16; oo++) acc[oo] = b3[og * 16 + oo];

    for (int c4 = 0; c4 < CC; c4 += 4) {
        float xv0 = zs[(c4 + 0) * 64 + tv];
        float xv1 = zs[(c4 + 1) * 64 + tv];
        float xv2 = zs[(c4 + 2) * 64 + tv];
        float xv3 = zs[(c4 + 3) * 64 + tv];
#pragma unroll
        for (int oo = 0; oo < 16; oo++) {
            float4 w = *reinterpret_cast<const float4*>(&w3s[(og * 16 + oo) * CC + c4]);
            acc[oo] = fmaf(w.x, xv0, acc[oo]);
            acc[oo] = fmaf(w.y, xv1, acc[oo]);
            acc[oo] = fmaf(w.z, xv2, acc[oo]);
            acc[oo] = fmaf(w.w, xv3, acc[oo]);
        }
    }

    float* op = out + (size_t)b * OUTC * (TT_ * VV) + tv0 + tv;
#pragma unroll
    for (int oo = 0; oo < 16; oo++) op[(size_t)(og * 16 + oo) * (TT_ * VV)] = acc[oo];
}

extern "C" void kernel_launch(void* const* d_in, const int* in_sizes, int n_in,
                              void* d_out, int out_size) {
    const float* x  = (const float*)d_in[0];
    const float* A  = (const float*)d_in[1];
    const float* w1 = (const float*)d_in[2];
    const float* b1 = (const float*)d_in[3];
    const float* w2 = (const float*)d_in[4];
    const float* b2 = (const float*)d_in[5];
    const float* w3 = (const float*)d_in[6];
    const float* b3 = (const float*)d_in[7];
    const float* w4 = (const float*)d_in[8];
    const float* b4 = (const float*)d_in[9];
    float* out = (float*)d_out;

    kA<<<BB, 256>>>(x, w1, b1, w2, b2);
    kB<<<dim3(CC, BB), 256>>>(x, A, w4, b4);
    kC<<<dim3((TT_ * VV) / 64, BB), 256>>>(w3, b3, out);
}

// round 3
// speedup vs baseline: 1.0032x; 1.0032x over previous
#include <cuda_runtime.h>
#include <math.h>

#define BB 32
#define CC 64
#define TT_ 128
#define VV 25
#define RR 8
#define TS 9
#define OUTC 64

typedef unsigned long long u64;

// scratch (allocation-free rule: device globals)
__device__ float g_xm[BB * CC * VV];                 // mean_t x
__device__ float g_dbuf[BB * RR * VV * VV];          // d[b,r,j,i]
__device__ float g_zbuf[(size_t)BB * CC * TT_ * VV]; // z[b,c,t,i]

__device__ __forceinline__ u64 pack2(float lo, float hi) {
    u64 r;
    asm("mov.b64 %0, {%1, %2};" : "=l"(r) : "f"(lo), "f"(hi));
    return r;
}
__device__ __forceinline__ void ffma2(u64& d, u64 a, u64 b) {
    asm("fma.rn.f32x2 %0, %1, %2, %0;" : "+l"(d) : "l"(a), "l"(b));
}

// ---------------- kA1: coalesced mean over T, one block per (b,c) ----------------
__global__ void __launch_bounds__(128) kA1(const float* __restrict__ x) {
    int c = blockIdx.x, b = blockIdx.y;
    int tid = threadIdx.x;
    __shared__ float xt[TT_ * VV];
    __shared__ float part[VV * 4];

    const float* xp = x + (size_t)(b * CC + c) * (TT_ * VV);
    for (int i = tid; i < TT_ * VV; i += 128) xt[i] = xp[i];
    __syncthreads();

    if (tid < VV * 4) {
        int v = tid >> 2, s = tid & 3;
        float acc = 0.f;
#pragma unroll 8
        for (int t = s; t < TT_; t += 4) acc += xt[t * VV + v];
        part[tid] = acc;
    }
    __syncthreads();
    if (tid < VV) {
        float m = (part[tid * 4] + part[tid * 4 + 1] + part[tid * 4 + 2] + part[tid * 4 + 3]) * (1.f / (float)TT_);
        g_xm[(b * CC + c) * VV + tid] = m;
    }
}

// ---------------- kA2: x1/x2 + d=tanh(x1-x2), one block per b ----------------
__global__ void __launch_bounds__(256) kA2(const float* __restrict__ w1, const float* __restrict__ b1,
                                           const float* __restrict__ w2, const float* __restrict__ b2) {
    int b = blockIdx.x;
    int tid = threadIdx.x;
    __shared__ float xm[CC * VV];
    __shared__ float x1s[RR * VV];
    __shared__ float x2s[RR * VV];

    const float* xmg = g_xm + b * (CC * VV);
    for (int i = tid; i < CC * VV; i += 256) {
        int c = i / VV, v = i % VV;          // g_xm stored [c][v]
        xm[c * VV + v] = xmg[i];
    }
    __syncthreads();

    for (int q = tid; q < 2 * RR * VV; q += 256) {
        int which = q / (RR * VV);
        int idx = q % (RR * VV);
        int r = idx / VV, v = idx % VV;
        const float* w = which ? w2 : w1;
        float s = 0.f;
#pragma unroll 8
        for (int c = 0; c < CC; c++) s = fmaf(w[r * CC + c], xm[c * VV + v], s);
        s += (which ? b2 : b1)[r];
        (which ? x2s : x1s)[idx] = s;
    }
    __syncthreads();

    float* db = g_dbuf + b * (RR * VV * VV);
    for (int idx = tid; idx < RR * VV * VV; idx += 256) {
        int r = idx / (VV * VV);
        int rem = idx % (VV * VV);
        int j = rem / VV, i = rem % VV;
        db[idx] = tanhf(x1s[r * VV + j] - x2s[r * VV + i]);
    }
}

// ---------------- kB: build W (duplicated float2) + dynamic conv (f32x2) -> z ----------------
__global__ void __launch_bounds__(256) kB(const float* __restrict__ x,
                                          const float* __restrict__ A,
                                          const float* __restrict__ w4, const float* __restrict__ b4) {
    int c = blockIdx.x;
    int b = blockIdx.y;
    int tid = threadIdx.x;

    __shared__ __align__(16) float2 W2s[VV * TS * VV];  // [j][k][i], each value duplicated -> 45KB
    __shared__ __align__(16) float xsT[VV * 140];       // [j][pad-time], stride 140

    const float* db = g_dbuf + b * (RR * VV * VV);

    // W[j,i,k] = A[j,i] + b4[c*9+k] + sum_r w4[c*9+k, r] * d[r,j,i], stored duplicated
    for (int p = tid; p < VV * VV; p += 256) {
        int j = p / VV, i = p % VV;
        float dr[RR];
#pragma unroll
        for (int r = 0; r < RR; r++) dr[r] = __ldg(db + r * (VV * VV) + p);
        float a = __ldg(A + p);
#pragma unroll
        for (int k = 0; k < TS; k++) {
            int o = c * TS + k;
            float s = a + __ldg(b4 + o);
#pragma unroll
            for (int r = 0; r < RR; r++) s = fmaf(__ldg(w4 + o * RR + r), dr[r], s);
            W2s[(j * TS + k) * VV + i] = make_float2(s, s);
        }
    }

    // stage x transposed + causal left pad (8 zeros)
    for (int idx = tid; idx < VV * 8; idx += 256) {
        int j = idx / 8, s0 = idx % 8;
        xsT[j * 140 + s0] = 0.f;
    }
    const float* xp = x + (size_t)(b * CC + c) * (TT_ * VV);
    for (int idx = tid; idx < TT_ * VV; idx += 256) {
        int t = idx / VV, j = idx % VV;
        xsT[j * 140 + t + 8] = xp[idx];
    }
    __syncthreads();

    int warp = tid >> 5, lane = tid & 31;
    int t0 = warp * 16;  // 8 warps * 16 t

    if (lane < VV) {
        u64 acc[8];
#pragma unroll
        for (int p = 0; p < 8; p++) acc[p] = 0ULL;  // (0.f, 0.f)

        const u64* wbase = reinterpret_cast<const u64*>(W2s) + lane;

        for (int j = 0; j < VV; j++) {
            float xr[24];
            const float4* xv = reinterpret_cast<const float4*>(&xsT[j * 140 + t0]);
#pragma unroll
            for (int q = 0; q < 6; q++) {
                float4 v = xv[q];
                xr[4 * q + 0] = v.x; xr[4 * q + 1] = v.y;
                xr[4 * q + 2] = v.z; xr[4 * q + 3] = v.w;
            }
            u64 pr[23];
#pragma unroll
            for (int m = 0; m < 23; m++) pr[m] = pack2(xr[m], xr[m + 1]);

            const u64* wrow = wbase + (j * TS) * VV;
#pragma unroll
            for (int k = 0; k < TS; k++) {
                u64 w2 = wrow[k * VV];  // duplicated pair, single LDS.64
#pragma unroll
                for (int p = 0; p < 8; p++) ffma2(acc[p], pr[2 * p + k], w2);
            }
        }
        float* zp = g_zbuf + (size_t)(b * CC + c) * (TT_ * VV) + lane;
#pragma unroll
        for (int p = 0; p < 8; p++) {
            float2 v = *reinterpret_cast<float2*>(&acc[p]);
            zp[(t0 + 2 * p) * VV] = v.x;
            zp[(t0 + 2 * p + 1) * VV] = v.y;
        }
    }
}

// ---------------- kC: out = w3 @ z + b3, f32x2 packed over adjacent tv ----------------
// 256 threads: tvp = tid&31 (32 tv-pairs = 64 tv), og = tid>>5 (8 groups x 8 o)
__global__ void __launch_bounds__(256) kC(const float* __restrict__ w3, const float* __restrict__ b3,
                                          float* __restrict__ out) {
    int b = blockIdx.y;
    int tv0 = blockIdx.x * 64;
    int tid = threadIdx.x;

    __shared__ __align__(16) float zs[CC * 64];      // 16KB
    __shared__ __align__(16) float2 w3d[OUTC * CC];  // duplicated weights, 32KB

    const float* zb = g_zbuf + (size_t)b * CC * (TT_ * VV);
    for (int i = tid; i < CC * 64; i += 256) {
        int cc = i >> 6, u = i & 63;
        zs[i] = zb[cc * (TT_ * VV) + tv0 + u];
    }
    for (int i = tid; i < OUTC * CC; i += 256) {
        float w = w3[i];
        w3d[i] = make_float2(w, w);
    }
    __syncthreads();

    int tvp = tid & 31, og = tid >> 5;
    u64 acc[8];
#pragma unroll
    for (int oo = 0; oo < 8; oo++) {
        float bb = b3[og * 8 + oo];
        acc[oo] = pack2(bb, bb);
    }

    const u64* wbase = reinterpret_cast<const u64*>(w3d) + (og * 8) * CC;
#pragma unroll 8
    for (int c = 0; c < CC; c++) {
        u64 xp2 = *reinterpret_cast<const u64*>(&zs[c * 64 + 2 * tvp]);
#pragma unroll
        for (int oo = 0; oo < 8; oo++) ffma2(acc[oo], xp2, wbase[oo * CC + c]);
    }

    float* ob = out + (size_t)b * OUTC * (TT_ * VV) + tv0 + 2 * tvp;
#pragma unroll
    for (int oo = 0; oo < 8; oo++) {
        *reinterpret_cast<float2*>(ob + (size_t)(og * 8 + oo) * (TT_ * VV)) =
            *reinterpret_cast<float2*>(&acc[oo]);
    }
}

extern "C" void kernel_launch(void* const* d_in, const int* in_sizes, int n_in,
                              void* d_out, int out_size) {
    const float* x  = (const float*)d_in[0];
    const float* A  = (const float*)d_in[1];
    const float* w1 = (const float*)d_in[2];
    const float* b1 = (const float*)d_in[3];
    const float* w2 = (const float*)d_in[4];
    const float* b2 = (const float*)d_in[5];
    const float* w3 = (const float*)d_in[6];
    const float* b3 = (const float*)d_in[7];
    const float* w4 = (const float*)d_in[8];
    const float* b4 = (const float*)d_in[9];
    float* out = (float*)d_out;

    kA1<<<dim3(CC, BB), 128>>>(x);
    kA2<<<BB, 256>>>(w1, b1, w2, b2);
    kB<<<dim3(CC, BB), 256>>>(x, A, w4, b4);
    kC<<<dim3((TT_ * VV) / 64, BB), 256>>>(w3, b3, out);
}